// round 6
// baseline (speedup 1.0000x reference)
#include <cuda_runtime.h>
#include <cuda_pipeline.h>

#define VOCABN 5000
#define NB 16
#define NS 128
#define NT 512
#define NL 257            // 2*NS + 1
#define ESTR 288          // emit scratch row stride (288*4 = 1152 = 9*128B)
#define NEGV (-1e30f)
#define ALPHA_W 0.2f
#define SMOOTH 0.1f
#define DPTH 8            // cp.async pipeline depth (power of two)
#define GB 1024           // gather blocks (NB * 64), 8 t-steps each

__device__ float g_emit[NB * NT * ESTR];   // 9.4 MB scratch, [b][t][l]

__device__ __forceinline__ float lae3(float a, float b, float c) {
    float m = fmaxf(a, fmaxf(b, c));
    float s = __expf(a - m) + __expf(b - m) + __expf(c - m);
    return m + __logf(s);
}

// ===== kernel 1: emit gather (scattered, massively parallel) + att loss =====
__global__ __launch_bounds__(288) void gather_att_kernel(
    const float* __restrict__ att,   // (16,128,5000)
    const float* __restrict__ ctc,   // (16,512,5000)
    const int*   __restrict__ tgt,   // (16,128)
    float* __restrict__ out)
{
    const int tid = threadIdx.x;
    const int blk = blockIdx.x;

    if (blk < GB) {
        // gather emit[b][t][l] = ctc[b][t][ext[l]] for 8 consecutive t
        const int b  = blk >> 6;              // blk / 64
        const int t0 = (blk & 63) << 3;       // 8 t's per block
        if (tid >= NL) return;
        int ext = 0;
        if (tid & 1) ext = __ldg(tgt + b * NS + (tid >> 1));
        const float* col = ctc + (size_t)b * NT * VOCABN + ext;
        float* dst = g_emit + ((size_t)b * NT + t0) * ESTR + tid;
        float v[8];
        #pragma unroll
        for (int i = 0; i < 8; ++i)
            v[i] = __ldg(col + (size_t)(t0 + i) * VOCABN);
        #pragma unroll
        for (int i = 0; i < 8; ++i)
            dst[i * ESTR] = v[i];
    } else {
        // label-smoothing row
        __shared__ float red[9];
        const int r = blk - GB;               // 0..2047
        const float* row = att + (size_t)r * VOCABN;
        const int tv = __ldg(tgt + r);

        float s = 0.0f;
        const float4* row4 = (const float4*)row;   // 5000 % 4 == 0
        for (int i = tid; i < VOCABN / 4; i += 288) {
            float4 v = row4[i];
            s += (v.x + v.y) + (v.z + v.w);
        }
        #pragma unroll
        for (int o = 16; o > 0; o >>= 1)
            s += __shfl_down_sync(0xffffffffu, s, o);
        const int wid = tid >> 5, lane = tid & 31;
        if (lane == 0) red[wid] = s;
        __syncthreads();
        if (tid == 0) {
            float total = 0.0f;
            #pragma unroll
            for (int w = 0; w < 9; ++w) total += red[w];
            float tl = __ldg(row + tv);
            const float conf = 1.0f - SMOOTH;
            const float off  = SMOOTH / (float)(VOCABN - 1);
            float per_row = -(off * total + (conf - off) * tl);
            atomicAdd(out, (ALPHA_W / 2048.0f) * per_row);
        }
    }
}

// ===== kernel 2: CTC forward scan, linear emit reads from L2-hot scratch =====
__global__ __launch_bounds__(288) void ctc_scan_kernel(
    const int* __restrict__ tgt,
    float* __restrict__ out)
{
    __shared__ float Sa[2][NL + 1];
    __shared__ float ring[DPTH * ESTR];

    const int tid = threadIdx.x;
    const int b   = blockIdx.x;

    const float* eb = g_emit + (size_t)b * NT * ESTR;   // [t][l], linear
    const int*   tb = tgt + b * NS;

    bool  allow2 = false;
    float a = NEGV;

    if (tid < NL) {
        if (tid & 1) {
            int ext = tb[tid >> 1];
            if (tid >= 3) {
                int prev = tb[(tid - 3) >> 1];
                allow2 = (ext != 0) && (ext != prev);
            }
        }
        a = (tid <= 1) ? __ldg(eb + tid) : NEGV;        // t = 0 init
        // prologue: stage emits for t = 1..DPTH, one commit group per step
        #pragma unroll
        for (int d = 0; d < DPTH; ++d) {
            __pipeline_memcpy_async(&ring[d * ESTR + tid],
                                    eb + (size_t)(1 + d) * ESTR + tid, 4);
            __pipeline_commit();
        }
    }

    int p = 0;
    for (int t = 1; t < NT; ++t) {
        const int s = (t - 1) & (DPTH - 1);
        if (tid < NL) {
            Sa[p][tid] = a;                      // publish alpha_{t-1}
            __pipeline_wait_prior(DPTH - 1);     // emit for step t landed
        }
        __syncthreads();
        if (tid < NL) {
            float e = ring[s * ESTR + tid];
            const int tp = t + DPTH;
            if (tp < NT)
                __pipeline_memcpy_async(&ring[s * ESTR + tid],
                                        eb + (size_t)tp * ESTR + tid, 4);
            __pipeline_commit();                 // exactly one group per step
            float am1 = (tid >= 1) ? Sa[p][tid - 1] : NEGV;
            float am2 = allow2     ? Sa[p][tid - 2] : NEGV;
            a = lae3(a, am1, am2) + e;
        }
        p ^= 1;
    }

    if (tid < NL) Sa[0][tid] = a;
    __syncthreads();
    if (tid == 0) {
        float ll = lae3(Sa[0][NL - 1], Sa[0][NL - 2], NEGV);
        float lb = -ll;
        if (lb > 1e20f) lb = 0.0f;               // zero_infinity
        atomicAdd(out, ((1.0f - ALPHA_W) / (float)(NB * NS)) * lb);
    }
}

extern "C" void kernel_launch(void* const* d_in, const int* in_sizes, int n_in,
                              void* d_out, int out_size) {
    const float* att = (const float*)d_in[0];
    const float* ctc = (const float*)d_in[1];
    const int*   tgt = (const int*)d_in[2];
    float* out = (float*)d_out;

    cudaMemsetAsync(out, 0, sizeof(float));
    gather_att_kernel<<<GB + NB * NS, 288>>>(att, ctc, tgt, out);
    ctc_scan_kernel<<<NB, 288>>>(tgt, out);
}

// round 7
// speedup vs baseline: 1.6367x; 1.6367x over previous
#include <cuda_runtime.h>
#include <cuda_pipeline.h>

#define VOCABN 5000
#define NB 16
#define NS 128
#define NT 512
#define NL 257            // 2*NS + 1
#define ESTR 264          // padded emit row stride (264*4 = 1056 bytes, 16B aligned)
#define ALPHA_W 0.2f
#define SMOOTH 0.1f
#define DPTH 8            // cp.async ring depth
#define GB 1024           // gather blocks: NB * 64, 8 t-steps each

__device__ float g_emit[NB * NT * ESTR];   // E = exp(ctc logit) gathered, 8.6 MB

// ===== kernel 1: parallel gather + exp (moves all MUFU off the serial path) =====
__global__ __launch_bounds__(288) void gather_kernel(
    const float* __restrict__ ctc,   // (16,512,5000)
    const int*   __restrict__ tgt)   // (16,128)
{
    const int tid = threadIdx.x;
    const int b  = blockIdx.x >> 6;
    const int t0 = (blockIdx.x & 63) << 3;
    if (tid >= ESTR) return;
    float* dst = g_emit + ((size_t)b * NT + t0) * ESTR + tid;
    if (tid < NL) {
        int ext = 0;
        if (tid & 1) ext = __ldg(tgt + b * NS + (tid >> 1));
        const float* col = ctc + (size_t)b * NT * VOCABN + ext;
        float v[8];
        #pragma unroll
        for (int i = 0; i < 8; ++i)
            v[i] = __expf(__ldg(col + (size_t)(t0 + i) * VOCABN));
        #pragma unroll
        for (int i = 0; i < 8; ++i) dst[i * ESTR] = v[i];
    } else {
        #pragma unroll
        for (int i = 0; i < 8; ++i) dst[i * ESTR] = 0.0f;
    }
}

// ===== kernel 2: warp-per-batch linear-domain scan (blocks 0..15) + att loss =====
__global__ __launch_bounds__(288) void scan_att_kernel(
    const float* __restrict__ att,   // (16,128,5000)
    const int*   __restrict__ tgt,
    float* __restrict__ out)
{
    __shared__ __align__(16) float ring[DPTH * ESTR];
    __shared__ float red[9];

    const int tid = threadIdx.x;
    const int blk = blockIdx.x;

    if (blk < NB) {
        if (tid >= 32) return;                 // single-warp scan, no __syncthreads
        const int lane = tid;
        const float* eb = g_emit + (size_t)blk * NT * ESTR;
        const int*   tb = tgt + blk * NS;

        // allow-2 flags for owned states s = 8*lane + j (j=0..7, s <= 255)
        float allowf[8];
        #pragma unroll
        for (int j = 0; j < 8; ++j) {
            int s = 8 * lane + j;
            float af = 0.0f;
            if ((s & 1) && s >= 3) {
                int e  = __ldg(tb + (s >> 1));
                int ep = __ldg(tb + (s >> 1) - 1);
                af = (e != 0 && e != ep) ? 1.0f : 0.0f;
            }
            allowf[j] = af;
        }

        // linear-domain init: alpha[0]=E[0][0], alpha[1]=E[0][1], rest 0
        float v[8], v8 = 0.0f;
        #pragma unroll
        for (int j = 0; j < 8; ++j) v[j] = 0.0f;
        if (lane == 0) { v[0] = __ldg(eb + 0); v[1] = __ldg(eb + 1); }

        // prologue: stage E for t = 1..DPTH (one commit group per step)
        #pragma unroll
        for (int d = 0; d < DPTH; ++d) {
            const float* src = eb + (size_t)(1 + d) * ESTR;
            __pipeline_memcpy_async(&ring[d * ESTR + 8 * lane],     src + 8 * lane,     16);
            __pipeline_memcpy_async(&ring[d * ESTR + 8 * lane + 4], src + 8 * lane + 4, 16);
            if (lane == 31)
                __pipeline_memcpy_async(&ring[d * ESTR + 256], src + 256, 4);
            __pipeline_commit();
        }

        float scale_log = 0.0f;
        for (int tt = 0; tt < 64; ++tt) {
            #pragma unroll
            for (int i = 0; i < 8; ++i) {
                const int t = 1 + tt * 8 + i;
                if (t < NT) {
                    __pipeline_wait_prior(DPTH - 1);     // E for step t landed
                    const float* rs = &ring[i * ESTR];
                    float E[8], E8;
                    #pragma unroll
                    for (int j = 0; j < 8; ++j) E[j] = rs[8 * lane + j];
                    E8 = rs[256];
                    // refill slot i for step t + DPTH (read-before-refill is safe:
                    // LDS issued above; LDGSTS smem write lands >=200cyc later)
                    const int tp = t + DPTH;
                    if (tp < NT) {
                        const float* src = eb + (size_t)tp * ESTR;
                        __pipeline_memcpy_async(&ring[i * ESTR + 8 * lane],     src + 8 * lane,     16);
                        __pipeline_memcpy_async(&ring[i * ESTR + 8 * lane + 4], src + 8 * lane + 4, 16);
                        if (lane == 31)
                            __pipeline_memcpy_async(&ring[i * ESTR + 256], src + 256, 4);
                    }
                    __pipeline_commit();                 // exactly one group per step

                    // boundary from lane-1: its old states 8*lane-1, 8*lane-2
                    float x1 = __shfl_up_sync(0xffffffffu, v[7], 1);
                    float x2 = __shfl_up_sync(0xffffffffu, v[6], 1);
                    if (lane == 0) { x1 = 0.0f; x2 = 0.0f; }

                    float n0 = (v[0] + x1)   + allowf[0] * x2;
                    float n1 = (v[1] + v[0]) + allowf[1] * x1;
                    float n2 = (v[2] + v[1]) + allowf[2] * v[0];
                    float n3 = (v[3] + v[2]) + allowf[3] * v[1];
                    float n4 = (v[4] + v[3]) + allowf[4] * v[2];
                    float n5 = (v[5] + v[4]) + allowf[5] * v[3];
                    float n6 = (v[6] + v[5]) + allowf[6] * v[4];
                    float n7 = (v[7] + v[6]) + allowf[7] * v[5];
                    float n8 = v8 + v[7];                // state 256: blank, no skip
                    v[0] = n0 * E[0]; v[1] = n1 * E[1];
                    v[2] = n2 * E[2]; v[3] = n3 * E[3];
                    v[4] = n4 * E[4]; v[5] = n5 * E[5];
                    v[6] = n6 * E[6]; v[7] = n7 * E[7];
                    v8   = n8 * E8;
                }
            }
            // renormalize every 8 steps: divide by warp max, accumulate log
            float m = v[0];
            #pragma unroll
            for (int j = 1; j < 8; ++j) m = fmaxf(m, v[j]);
            m = fmaxf(m, v8);
            #pragma unroll
            for (int o = 16; o > 0; o >>= 1)
                m = fmaxf(m, __shfl_xor_sync(0xffffffffu, m, o));
            float r = __frcp_rn(m);
            #pragma unroll
            for (int j = 0; j < 8; ++j) v[j] *= r;
            v8 *= r;
            scale_log += __logf(m);
        }

        if (lane == 31) {
            float tot = v[7] + v8;                 // states 255 + 256
            float ll = __logf(tot) + scale_log;
            float lb = -ll;
            if (!(lb < 1e20f)) lb = 0.0f;          // zero_infinity (also catches inf/nan)
            atomicAdd(out, ((1.0f - ALPHA_W) / (float)(NB * NS)) * lb);
        }
    } else {
        // ================= label-smoothing row `blk - NB` =================
        const int r = blk - NB;                    // 0..2047
        const float* row = att + (size_t)r * VOCABN;
        const int tv = __ldg(tgt + r);

        float s = 0.0f;
        const float4* row4 = (const float4*)row;   // 5000 % 4 == 0
        for (int i = tid; i < VOCABN / 4; i += 288) {
            float4 v = row4[i];
            s += (v.x + v.y) + (v.z + v.w);
        }
        #pragma unroll
        for (int o = 16; o > 0; o >>= 1)
            s += __shfl_down_sync(0xffffffffu, s, o);
        const int wid = tid >> 5, lane = tid & 31;
        if (lane == 0) red[wid] = s;
        __syncthreads();
        if (tid == 0) {
            float total = 0.0f;
            #pragma unroll
            for (int w = 0; w < 9; ++w) total += red[w];
            float tl = __ldg(row + tv);
            const float conf = 1.0f - SMOOTH;
            const float off  = SMOOTH / (float)(VOCABN - 1);
            float per_row = -(off * total + (conf - off) * tl);
            atomicAdd(out, (ALPHA_W / 2048.0f) * per_row);
        }
    }
}

extern "C" void kernel_launch(void* const* d_in, const int* in_sizes, int n_in,
                              void* d_out, int out_size) {
    const float* att = (const float*)d_in[0];
    const float* ctc = (const float*)d_in[1];
    const int*   tgt = (const int*)d_in[2];
    float* out = (float*)d_out;

    cudaMemsetAsync(out, 0, sizeof(float));
    gather_kernel<<<GB, 288>>>(ctc, tgt);
    scan_att_kernel<<<NB + NB * NS, 288>>>(att, tgt, out);
}

// round 8
// speedup vs baseline: 2.6988x; 1.6489x over previous
#include <cuda_runtime.h>
#include <cuda_pipeline.h>

#define VOCABN 5000
#define NB 16
#define NS 128
#define NT 512
#define NL 257            // 2*NS + 1
#define ESTR 264          // emit scratch row stride in g_emit
#define RS 256            // ring slot stride (256 floats = 1KB, states 0..255)
#define ALPHA_W 0.2f
#define SMOOTH 0.1f
#define DPTH 8            // cp.async ring depth
#define GB 1024           // gather blocks: NB * 64, 8 t-steps each
#define TM 255            // meet point: ll = sum_l alpha_255[l] * C(beta_256)[l]

__device__ float g_emit[NB * NT * ESTR];   // E = exp(ctc logit), 8.6 MB

// ===== kernel 1: parallel gather + exp =====
__global__ __launch_bounds__(288) void gather_kernel(
    const float* __restrict__ ctc, const int* __restrict__ tgt)
{
    const int tid = threadIdx.x;
    const int b  = blockIdx.x >> 6;
    const int t0 = (blockIdx.x & 63) << 3;
    if (tid >= ESTR) return;
    float* dst = g_emit + ((size_t)b * NT + t0) * ESTR + tid;
    if (tid < NL) {
        int ext = 0;
        if (tid & 1) ext = __ldg(tgt + b * NS + (tid >> 1));
        const float* col = ctc + (size_t)b * NT * VOCABN + ext;
        float v[8];
        #pragma unroll
        for (int i = 0; i < 8; ++i)
            v[i] = __expf(__ldg(col + (size_t)(t0 + i) * VOCABN));
        #pragma unroll
        for (int i = 0; i < 8; ++i) dst[i * ESTR] = v[i];
    } else {
        #pragma unroll
        for (int i = 0; i < 8; ++i) dst[i * ESTR] = 0.0f;
    }
}

// allow-2 into state x (forward table)
__device__ __forceinline__ float a2_into(const int* tb, int x) {
    if ((x & 1) && x >= 3 && x < NL) {
        int e  = __ldg(tb + (x >> 1));
        int ep = __ldg(tb + (x >> 1) - 1);
        return (e != 0 && e != ep) ? 1.0f : 0.0f;
    }
    return 0.0f;
}

// ===== kernel 2: fwd+bwd meet-in-the-middle scan (blocks 0..15) + att =====
__global__ __launch_bounds__(288) void scan_att_kernel(
    const float* __restrict__ att, const int* __restrict__ tgt,
    float* __restrict__ out)
{
    __shared__ __align__(16) float ringF[DPTH * RS];
    __shared__ __align__(16) float ringB[DPTH * RS];
    __shared__ float aS[264], bS[264];
    __shared__ float sFS, sBS;
    __shared__ float red[9];

    const int tid = threadIdx.x;
    const int blk = blockIdx.x;

    if (blk < NB) {
        const int lane = tid & 31;
        const float* eb = g_emit + (size_t)blk * NT * ESTR;
        const int*   tb = tgt + blk * NS;

        if (tid < 32) {
            // ---------------- forward warp: t = 1..255 ----------------
            float a2[8];
            #pragma unroll
            for (int j = 0; j < 8; ++j) a2[j] = a2_into(tb, 8 * lane + j);

            float v[8], v8 = 0.0f;
            #pragma unroll
            for (int j = 0; j < 8; ++j) v[j] = 0.0f;
            if (lane == 0) { v[0] = __ldg(eb + 0); v[1] = __ldg(eb + 1); }

            #pragma unroll
            for (int d = 0; d < DPTH; ++d) {
                const float* src = eb + (size_t)(1 + d) * ESTR + 8 * lane;
                __pipeline_memcpy_async(&ringF[d * RS + 8 * lane],     src,     16);
                __pipeline_memcpy_async(&ringF[d * RS + 8 * lane + 4], src + 4, 16);
                __pipeline_commit();
            }

            float sF = 0.0f;
            for (int tt = 0; tt < 32; ++tt) {
                #pragma unroll
                for (int i = 0; i < 8; ++i) {
                    const int t = 1 + tt * 8 + i;
                    if (t <= TM) {
                        __pipeline_wait_prior(DPTH - 1);
                        float4 Ea = *(const float4*)&ringF[i * RS + 8 * lane];
                        float4 Eb = *(const float4*)&ringF[i * RS + 8 * lane + 4];
                        const int tp = t + DPTH;
                        if (tp <= TM) {
                            const float* src = eb + (size_t)tp * ESTR + 8 * lane;
                            __pipeline_memcpy_async(&ringF[i * RS + 8 * lane],     src,     16);
                            __pipeline_memcpy_async(&ringF[i * RS + 8 * lane + 4], src + 4, 16);
                        }
                        __pipeline_commit();
                        float E8 = __shfl_sync(0xffffffffu, Ea.x, 0);  // blank == state 0
                        float x1 = __shfl_up_sync(0xffffffffu, v[7], 1);
                        float x2 = __shfl_up_sync(0xffffffffu, v[6], 1);
                        if (lane == 0) { x1 = 0.0f; x2 = 0.0f; }
                        float n0 = (v[0] + x1)   + a2[0] * x2;
                        float n1 = (v[1] + v[0]) + a2[1] * x1;
                        float n2 = (v[2] + v[1]) + a2[2] * v[0];
                        float n3 = (v[3] + v[2]) + a2[3] * v[1];
                        float n4 = (v[4] + v[3]) + a2[4] * v[2];
                        float n5 = (v[5] + v[4]) + a2[5] * v[3];
                        float n6 = (v[6] + v[5]) + a2[6] * v[4];
                        float n7 = (v[7] + v[6]) + a2[7] * v[5];
                        float n8 = v8 + v[7];
                        v[0] = n0 * Ea.x; v[1] = n1 * Ea.y;
                        v[2] = n2 * Ea.z; v[3] = n3 * Ea.w;
                        v[4] = n4 * Eb.x; v[5] = n5 * Eb.y;
                        v[6] = n6 * Eb.z; v[7] = n7 * Eb.w;
                        v8   = n8 * E8;
                    }
                }
                float m = v[0];
                #pragma unroll
                for (int j = 1; j < 8; ++j) m = fmaxf(m, v[j]);
                m = fmaxf(m, v8);
                #pragma unroll
                for (int o = 16; o > 0; o >>= 1)
                    m = fmaxf(m, __shfl_xor_sync(0xffffffffu, m, o));
                float r = __frcp_rn(m);
                #pragma unroll
                for (int j = 0; j < 8; ++j) v[j] *= r;
                v8 *= r;
                sF += __logf(m);
            }
            #pragma unroll
            for (int j = 0; j < 8; ++j) aS[8 * lane + j] = v[j];
            if (lane == 31) aS[256] = v8;
            if (lane == 0) sFS = sF;
        } else if (tid < 64) {
            // ---------------- backward warp: t = 510..256 (init 511) ----------------
            float a2b[8];
            #pragma unroll
            for (int j = 0; j < 8; ++j) a2b[j] = a2_into(tb, 8 * lane + j + 2);

            float v[8], v8 = 0.0f;
            #pragma unroll
            for (int j = 0; j < 8; ++j) v[j] = 0.0f;
            if (lane == 31) {
                const float* e511 = eb + (size_t)511 * ESTR;
                v[7] = __ldg(e511 + 255);
                v8   = __ldg(e511 + 0);          // state 256 emission = blank
            }

            #pragma unroll
            for (int d = 0; d < DPTH; ++d) {
                const float* src = eb + (size_t)(510 - d) * ESTR + 8 * lane;
                __pipeline_memcpy_async(&ringB[d * RS + 8 * lane],     src,     16);
                __pipeline_memcpy_async(&ringB[d * RS + 8 * lane + 4], src + 4, 16);
                __pipeline_commit();
            }

            float sB = 0.0f;
            for (int tt = 0; tt < 32; ++tt) {
                #pragma unroll
                for (int i = 0; i < 8; ++i) {
                    const int t = 510 - (tt * 8 + i);
                    if (t >= TM + 1) {
                        __pipeline_wait_prior(DPTH - 1);
                        float4 Ea = *(const float4*)&ringB[i * RS + 8 * lane];
                        float4 Eb = *(const float4*)&ringB[i * RS + 8 * lane + 4];
                        const int tp = t - DPTH;
                        if (tp >= TM + 1) {
                            const float* src = eb + (size_t)tp * ESTR + 8 * lane;
                            __pipeline_memcpy_async(&ringB[i * RS + 8 * lane],     src,     16);
                            __pipeline_memcpy_async(&ringB[i * RS + 8 * lane + 4], src + 4, 16);
                        }
                        __pipeline_commit();
                        float E8 = __shfl_sync(0xffffffffu, Ea.x, 0);
                        float x1 = __shfl_down_sync(0xffffffffu, v[0], 1);  // state 8l+8
                        float x2 = __shfl_down_sync(0xffffffffu, v[1], 1);  // state 8l+9
                        if (lane == 31) { x1 = v8; x2 = 0.0f; }
                        float n0 = (v[0] + v[1]) + a2b[0] * v[2];
                        float n1 = (v[1] + v[2]) + a2b[1] * v[3];
                        float n2 = (v[2] + v[3]) + a2b[2] * v[4];
                        float n3 = (v[3] + v[4]) + a2b[3] * v[5];
                        float n4 = (v[4] + v[5]) + a2b[4] * v[6];
                        float n5 = (v[5] + v[6]) + a2b[5] * v[7];
                        float n6 = (v[6] + v[7]) + a2b[6] * x1;
                        float n7 = (v[7] + x1)   + a2b[7] * x2;
                        float n8 = v8;                        // state 256: self only
                        v[0] = n0 * Ea.x; v[1] = n1 * Ea.y;
                        v[2] = n2 * Ea.z; v[3] = n3 * Ea.w;
                        v[4] = n4 * Eb.x; v[5] = n5 * Eb.y;
                        v[6] = n6 * Eb.z; v[7] = n7 * Eb.w;
                        v8   = n8 * E8;
                    }
                }
                float m = v[0];
                #pragma unroll
                for (int j = 1; j < 8; ++j) m = fmaxf(m, v[j]);
                m = fmaxf(m, v8);
                #pragma unroll
                for (int o = 16; o > 0; o >>= 1)
                    m = fmaxf(m, __shfl_xor_sync(0xffffffffu, m, o));
                float r = __frcp_rn(m);
                #pragma unroll
                for (int j = 0; j < 8; ++j) v[j] *= r;
                v8 *= r;
                sB += __logf(m);
            }
            #pragma unroll
            for (int j = 0; j < 8; ++j) bS[8 * lane + j] = v[j];
            if (lane == 31) {
                bS[256] = v8; bS[257] = 0.0f; bS[258] = 0.0f;
            }
            if (lane == 0) sBS = sB;
        }

        __syncthreads();

        if (tid < 32) {
            // join: ll = log( sum_l aS[l] * C[l] ) + sF + sB
            float dot = 0.0f;
            #pragma unroll
            for (int j = 0; j < 8; ++j) {
                int s = 8 * lane + j;
                float C = bS[s] + bS[s + 1] + a2_into(tb, s + 2) * bS[s + 2];
                dot += aS[s] * C;
            }
            if (lane == 31) dot += aS[256] * bS[256];
            #pragma unroll
            for (int o = 16; o > 0; o >>= 1)
                dot += __shfl_xor_sync(0xffffffffu, dot, o);
            if (lane == 0) {
                float ll = __logf(dot) + sFS + sBS;
                float lb = -ll;
                if (!(lb < 1e20f)) lb = 0.0f;      // zero_infinity (inf/nan too)
                atomicAdd(out, ((1.0f - ALPHA_W) / (float)(NB * NS)) * lb);
            }
        }
    } else {
        // ================= label-smoothing row `blk - NB` =================
        const int r = blk - NB;
        const float* row = att + (size_t)r * VOCABN;
        const int tv = __ldg(tgt + r);

        float s = 0.0f;
        const float4* row4 = (const float4*)row;
        for (int i = tid; i < VOCABN / 4; i += 288) {
            float4 v = row4[i];
            s += (v.x + v.y) + (v.z + v.w);
        }
        #pragma unroll
        for (int o = 16; o > 0; o >>= 1)
            s += __shfl_down_sync(0xffffffffu, s, o);
        const int wid = tid >> 5, lane = tid & 31;
        if (lane == 0) red[wid] = s;
        __syncthreads();
        if (tid == 0) {
            float total = 0.0f;
            #pragma unroll
            for (int w = 0; w < 9; ++w) total += red[w];
            float tl = __ldg(row + tv);
            const float conf = 1.0f - SMOOTH;
            const float off  = SMOOTH / (float)(VOCABN - 1);
            float per_row = -(off * total + (conf - off) * tl);
            atomicAdd(out, (ALPHA_W / 2048.0f) * per_row);
        }
    }
}

extern "C" void kernel_launch(void* const* d_in, const int* in_sizes, int n_in,
                              void* d_out, int out_size) {
    const float* att = (const float*)d_in[0];
    const float* ctc = (const float*)d_in[1];
    const int*   tgt = (const int*)d_in[2];
    float* out = (float*)d_out;

    cudaMemsetAsync(out, 0, sizeof(float));
    gather_kernel<<<GB, 288>>>(ctc, tgt);
    scan_att_kernel<<<NB + NB * NS, 288>>>(att, tgt, out);
}